// round 14
// baseline (speedup 1.0000x reference)
#include <cuda_runtime.h>
#include <cuda_bf16.h>
#include <cstdint>

// Problem constants (fixed shapes)
#define B_SZ   256
#define T_SZ   512
#define EMB    128
#define HID    256
#define NCLS   32000

// Scratch: h0 at last timestep, stored bf16 for tensor-core GEMM
__device__ __nv_bfloat16 g_h0[B_SZ * HID];

// ---------------------------------------------------------------------------
// Kernel 1: h0_last[b, h] for the 256 last-timestep tokens. (validated)
// ---------------------------------------------------------------------------
__global__ void __launch_bounds__(256) lstm_h0_kernel(
    const int* __restrict__ X, const float* __restrict__ C_table,
    const float* __restrict__ U_i, const float* __restrict__ b_i,
    const float* __restrict__ U_c, const float* __restrict__ b_c,
    const float* __restrict__ U_o, const float* __restrict__ b_o)
{
    __shared__ float E_s[8][EMB];
    const int tid = threadIdx.x;
    const int b0  = blockIdx.y * 8;

    for (int i = tid; i < 8 * EMB; i += 256) {
        int b = i >> 7;
        int e = i & (EMB - 1);
        int tok = X[(b0 + b) * T_SZ + (T_SZ - 1)];
        E_s[b][e] = C_table[tok * EMB + e];
    }
    __syncthreads();

    const int h    = blockIdx.x * 64 + (tid & 63);
    const int bsub = tid >> 6;
    const int r0   = bsub * 2;

    float ai[2], ag[2], ao[2];
    const float bi = b_i[h], bc = b_c[h], bo = b_o[h];
#pragma unroll
    for (int r = 0; r < 2; r++) { ai[r] = bi; ag[r] = bc; ao[r] = bo; }

#pragma unroll 4
    for (int e = 0; e < EMB; e++) {
        float ui = U_i[e * HID + h];
        float uc = U_c[e * HID + h];
        float uo = U_o[e * HID + h];
#pragma unroll
        for (int r = 0; r < 2; r++) {
            float ev = E_s[r0 + r][e];
            ai[r] = fmaf(ev, ui, ai[r]);
            ag[r] = fmaf(ev, uc, ag[r]);
            ao[r] = fmaf(ev, uo, ao[r]);
        }
    }

#pragma unroll
    for (int r = 0; r < 2; r++) {
        float i0 = 1.0f / (1.0f + __expf(-ai[r]));
        float g0 = tanhf(ag[r]);
        float o0 = 1.0f / (1.0f + __expf(-ao[r]));
        float c0 = i0 * g0;
        float h0 = o0 * tanhf(c0);
        g_h0[(b0 + r0 + r) * HID + h] = __float2bfloat16(h0);
    }
}

// ---------------------------------------------------------------------------
// Kernel 2: logits[256, 32000] = h0 @ W_w^T + b_out
// Balanced persistent bf16 mma.sync GEMM. B path is a 3-stage smem pipeline:
//   cp.async fp32 -> staging (3 slots) -> single in-smem convert per group
//   -> bf16 buffer (2 slots, stride 56) -> ldmatrix.x4 B fragments.
// Removes the 4x-redundant consumer LDS+CVT of R12 with zero gmem prep cost.
//   GRID = 125 CTAs x 512 thr; 2 tiles per CTA (bid, bid+125); 16 phases;
//   CHUNK_K=32; wait_group 1; per-wn-group named barriers (R12, validated).
// ---------------------------------------------------------------------------
#define BM      256
#define BN      128
#define ASTR    264              // A_s row stride in bf16 (528B = 33*16)
#define CHUNK_K 32
#define NCHUNK  8                // chunks per tile
#define NPHASE  16               // 2 tiles x 8 chunks
#define SSTR    40               // staging row stride, fp32 (160B)
#define SBUF    (BN * SSTR)      // one staging slot, floats (5120 = 20480B)
#define NSTG    3
#define BSTRB   56               // bf16 buf row stride (112B: aligned + 8-bank)
#define BBUF16  (BN * BSTRB)     // one bf16 slot, elems (7168 = 14336B)
#define GRID2   125
#define NTILES  (NCLS / BN)      // 250

#define SM_A    0
#define SM_STG  (BM * ASTR * 2)            // 135168
#define SM_B16  (SM_STG + NSTG * SBUF * 4) // 135168 + 61440 = 196608
#define SM_TOT  (SM_B16 + 2 * BBUF16 * 2)  // 196608 + 28672 = 225280

__device__ __forceinline__ void cp16(void* dst_smem, const void* src) {
    uint32_t d = (uint32_t)__cvta_generic_to_shared(dst_smem);
    asm volatile("cp.async.cg.shared.global [%0], [%1], 16;" :: "r"(d), "l"(src));
}
__device__ __forceinline__ void cp_commit() {
    asm volatile("cp.async.commit_group;" ::: "memory");
}
__device__ __forceinline__ void cp_wait1() {
    asm volatile("cp.async.wait_group 1;" ::: "memory");
}
__device__ __forceinline__ void cp_wait2g() {
    asm volatile("cp.async.wait_group 2;" ::: "memory");
}
__device__ __forceinline__ void group_bar(int wn) {
    asm volatile("bar.sync %0, 128;" :: "r"(1 + wn) : "memory");
}

// Issue this wn-group's 32 rows of one fp32 W chunk into staging slot `dst`.
__device__ __forceinline__ void issue_b_stage(
    float* dst, const float* __restrict__ W_w, int n0, int ck,
    int wn, int gidx)
{
#pragma unroll
    for (int k = 0; k < 2; k++) {
        int idx = gidx + k * 128;          // 0..255
        int rl  = idx >> 3;                // local row 0..31
        int seg = idx & 7;                 // 8 segs * 16B
        int row = wn * 32 + rl;
        cp16(dst + row * SSTR + seg * 4,
             W_w + (size_t)(n0 + row) * HID + ck * CHUNK_K + seg * 4);
    }
}

// Convert this wn-group's 32 rows: staging fp32 -> bf16 buf. 8 elems/thread.
__device__ __forceinline__ void convert_rows(
    const float* stg, __nv_bfloat16* dst, int wn, int gidx)
{
    int rl  = gidx >> 2;                   // local row 0..31
    int seg = gidx & 3;                    // 8 fp32 = 32B
    int row = wn * 32 + rl;
    const float4* s = (const float4*)(stg + row * SSTR + seg * 8);
    float4 v0 = s[0];
    float4 v1 = s[1];
    __nv_bfloat162 p0 = __floats2bfloat162_rn(v0.x, v0.y);
    __nv_bfloat162 p1 = __floats2bfloat162_rn(v0.z, v0.w);
    __nv_bfloat162 p2 = __floats2bfloat162_rn(v1.x, v1.y);
    __nv_bfloat162 p3 = __floats2bfloat162_rn(v1.z, v1.w);
    uint4 u;
    u.x = *(uint32_t*)&p0; u.y = *(uint32_t*)&p1;
    u.z = *(uint32_t*)&p2; u.w = *(uint32_t*)&p3;
    *(uint4*)(dst + row * BSTRB + seg * 8) = u;
}

__global__ void __launch_bounds__(512, 1) logits_kernel(
    const float* __restrict__ W_w, const float* __restrict__ b_out,
    float* __restrict__ out)
{
    extern __shared__ char smem_raw[];
    __nv_bfloat16* A_s  = (__nv_bfloat16*)(smem_raw + SM_A);    // [256][ASTR]
    float*         STG  = (float*)(smem_raw + SM_STG);          // 3*[128][SSTR]
    __nv_bfloat16* B16  = (__nv_bfloat16*)(smem_raw + SM_B16);  // 2*[128][BSTRB]

    const int tid = threadIdx.x;
    const int bid = blockIdx.x;
    const int n0_t0 = bid * BN;                 // tile 0
    const int n0_t1 = (bid + GRID2) * BN;       // tile 1

    const int wid  = tid >> 5;
    const int lane = tid & 31;
    const int wm   = wid >> 2;      // 0..3 -> M offset wm*64
    const int wn   = wid & 3;       // 0..3 -> N offset wn*32 (B row group)
    const int gidx = wm * 32 + lane;           // group-local index 0..127
    const int gr   = lane >> 2;
    const int tig  = lane & 3;
    // A ldmatrix lane mapping (validated):
    const int lm_row = (lane & 15);
    const int lm_col = ((lane >> 4) & 1) << 3;
    // B ldmatrix lane mapping (validated in R13):
    const int bl_row = ((lane >> 4) << 3) + (lane & 7);   // n row within 16
    const int bl_col = ((lane >> 3) & 1) << 3;            // k half (elems)

    // --- prologue: A + chunks 0..2 ---
    {
        const char* src = (const char*)g_h0;
#pragma unroll
        for (int k = 0; k < 16; k++) {
            int idx = tid + k * 512;       // 8192 segs (256 rows x 32 segs)
            int row = idx >> 5;
            int seg = idx & 31;
            cp16((char*)A_s + row * (ASTR * 2) + seg * 16,
                 src + row * (HID * 2) + seg * 16);
        }
    }
    issue_b_stage(STG + 0 * SBUF, W_w, n0_t0, 0, wn, gidx); cp_commit(); // G0: A+c0
    issue_b_stage(STG + 1 * SBUF, W_w, n0_t0, 1, wn, gidx); cp_commit(); // G1: c1
    issue_b_stage(STG + 2 * SBUF, W_w, n0_t0, 2, wn, gidx); cp_commit(); // G2: c2

    cp_wait2g();         // G0 done: A + chunk0 (per thread)
    __syncthreads();     // A + chunk0 visible CTA-wide
    convert_rows(STG + 0 * SBUF, B16 + 0 * BBUF16, wn, gidx);  // c0 -> bf16[0]

    float acc[4][4][4];
#pragma unroll
    for (int mi = 0; mi < 4; mi++)
#pragma unroll
        for (int ni = 0; ni < 4; ni++)
#pragma unroll
            for (int r = 0; r < 4; r++) acc[mi][ni][r] = 0.0f;

#pragma unroll
    for (int g = 0; g < NPHASE; g++) {
        const int c = g & 7;                          // chunk within tile
        cp_wait1();          // chunk g+1 staged (groups 0..g+1 complete)
        group_bar(wn);       // staged data + bf16[g&1] conversions visible

        // ---- issue chunk g+3 into staging slot (g+3)%3 (held chunk g,
        //      converted in phase g-1; bar-separated -> safe) ----
        if (g + 3 < NPHASE) {
            int gi  = g + 3;
            int nn0 = (gi < NCHUNK) ? n0_t0 : n0_t1;
            issue_b_stage(STG + (gi % 3) * SBUF, W_w, nn0, gi & 7, wn, gidx);
        }
        cp_commit();         // unconditional: exact group numbering

        // ---- convert chunk g+1 -> bf16[(g+1)&1] (old content = chunk g-1,
        //      consumed before this phase's bar) ----
        if (g + 1 < NPHASE)
            convert_rows(STG + ((g + 1) % 3) * SBUF,
                         B16 + ((g + 1) & 1) * BBUF16, wn, gidx);

        // ---- compute 2 kk steps of chunk g from bf16[g&1] ----
        const __nv_bfloat16* Bb = B16 + (g & 1) * BBUF16;
#pragma unroll
        for (int kkl = 0; kkl < CHUNK_K / 16; kkl++) {
            const int kbg = c * CHUNK_K + kkl * 16;   // K offset in A
            const int kbl = kkl * 16;                 // K offset in B buf
            uint32_t a[4][4];
#pragma unroll
            for (int mi = 0; mi < 4; mi++) {
                uint32_t addr = (uint32_t)__cvta_generic_to_shared(
                    &A_s[(wm * 64 + mi * 16 + lm_row) * ASTR + kbg + lm_col]);
                asm volatile(
                    "ldmatrix.sync.aligned.m8n8.x4.shared.b16 {%0,%1,%2,%3}, [%4];"
                    : "=r"(a[mi][0]), "=r"(a[mi][1]), "=r"(a[mi][2]), "=r"(a[mi][3])
                    : "r"(addr));
            }
            uint32_t bmat[2][4];  // [h][tile]: h covers n rows wn*32+h*16..+15
#pragma unroll
            for (int h = 0; h < 2; h++) {
                uint32_t addr = (uint32_t)__cvta_generic_to_shared(
                    &Bb[(wn * 32 + h * 16 + bl_row) * BSTRB + kbl + bl_col]);
                asm volatile(
                    "ldmatrix.sync.aligned.m8n8.x4.shared.b16 {%0,%1,%2,%3}, [%4];"
                    : "=r"(bmat[h][0]), "=r"(bmat[h][1]),
                      "=r"(bmat[h][2]), "=r"(bmat[h][3])
                    : "r"(addr));
            }
#pragma unroll
            for (int mi = 0; mi < 4; mi++) {
#pragma unroll
                for (int ni = 0; ni < 4; ni++) {
                    const int h = ni >> 1;
                    const int s = (ni & 1) * 2;
                    asm volatile(
                        "mma.sync.aligned.m16n8k16.row.col.f32.bf16.bf16.f32 "
                        "{%0,%1,%2,%3}, {%4,%5,%6,%7}, {%8,%9}, {%0,%1,%2,%3};"
                        : "+f"(acc[mi][ni][0]), "+f"(acc[mi][ni][1]),
                          "+f"(acc[mi][ni][2]), "+f"(acc[mi][ni][3])
                        : "r"(a[mi][0]), "r"(a[mi][1]), "r"(a[mi][2]), "r"(a[mi][3]),
                          "r"(bmat[h][s]), "r"(bmat[h][s + 1]));
                }
            }
        }

        // ---- tile epilogue after its last chunk (warp-local; no sync) ----
        if (c == NCHUNK - 1) {
            const int n0 = (g < NCHUNK) ? n0_t0 : n0_t1;
            float bo0[4], bo1[4];
#pragma unroll
            for (int ni = 0; ni < 4; ni++) {
                int col = n0 + wn * 32 + ni * 8 + tig * 2;
                bo0[ni] = b_out[col];
                bo1[ni] = b_out[col + 1];
            }
#pragma unroll
            for (int mi = 0; mi < 4; mi++) {
                int row = wm * 64 + mi * 16 + gr;
#pragma unroll
                for (int ni = 0; ni < 4; ni++) {
                    int col = n0 + wn * 32 + ni * 8 + tig * 2;
                    float2 v0 = make_float2(acc[mi][ni][0] + bo0[ni],
                                            acc[mi][ni][1] + bo1[ni]);
                    float2 v1 = make_float2(acc[mi][ni][2] + bo0[ni],
                                            acc[mi][ni][3] + bo1[ni]);
                    *(float2*)(&out[(size_t)row * NCLS + col])       = v0;
                    *(float2*)(&out[(size_t)(row + 8) * NCLS + col]) = v1;
                }
            }
#pragma unroll
            for (int mi = 0; mi < 4; mi++)
#pragma unroll
                for (int ni = 0; ni < 4; ni++)
#pragma unroll
                    for (int r = 0; r < 4; r++) acc[mi][ni][r] = 0.0f;
        }
    }
}

// ---------------------------------------------------------------------------
// Launcher
// Input order: 0=X 1=C_table 2=U_i 3=V_i 4=b_i 5=U_f 6=V_f 7=b_f
//  8=U_c 9=V_c 10=b_c 11=U_o 12=V_o 13=b_o 14..25=layer1 (unused) 26=W_w 27=b_out
// ---------------------------------------------------------------------------
extern "C" void kernel_launch(void* const* d_in, const int* in_sizes, int n_in,
                              void* d_out, int out_size)
{
    const int*   X       = (const int*)d_in[0];
    const float* C_table = (const float*)d_in[1];
    const float* U_i     = (const float*)d_in[2];
    const float* b_i     = (const float*)d_in[4];
    const float* U_c     = (const float*)d_in[8];
    const float* b_c     = (const float*)d_in[10];
    const float* U_o     = (const float*)d_in[11];
    const float* b_o     = (const float*)d_in[13];
    const float* W_w     = (const float*)d_in[26];
    const float* b_out   = (const float*)d_in[27];
    float* out = (float*)d_out;

    dim3 grid1(4, 32);
    lstm_h0_kernel<<<grid1, 256>>>(X, C_table, U_i, b_i, U_c, b_c, U_o, b_o);

    cudaFuncSetAttribute(logits_kernel,
                         cudaFuncAttributeMaxDynamicSharedMemorySize, SM_TOT);
    logits_kernel<<<GRID2, 512, SM_TOT>>>(W_w, b_out, out);
}

// round 16
// speedup vs baseline: 1.0336x; 1.0336x over previous
#include <cuda_runtime.h>
#include <cuda_bf16.h>
#include <cstdint>

// Problem constants (fixed shapes)
#define B_SZ   256
#define T_SZ   512
#define EMB    128
#define HID    256
#define NCLS   32000

// Scratch: h0 at last timestep, stored bf16 for tensor-core GEMM
__device__ __nv_bfloat16 g_h0[B_SZ * HID];

// ---------------------------------------------------------------------------
// Kernel 1: h0_last[b, h] for the 256 last-timestep tokens. (validated)
// ---------------------------------------------------------------------------
__global__ void __launch_bounds__(256) lstm_h0_kernel(
    const int* __restrict__ X, const float* __restrict__ C_table,
    const float* __restrict__ U_i, const float* __restrict__ b_i,
    const float* __restrict__ U_c, const float* __restrict__ b_c,
    const float* __restrict__ U_o, const float* __restrict__ b_o)
{
    __shared__ float E_s[8][EMB];
    const int tid = threadIdx.x;
    const int b0  = blockIdx.y * 8;

    for (int i = tid; i < 8 * EMB; i += 256) {
        int b = i >> 7;
        int e = i & (EMB - 1);
        int tok = X[(b0 + b) * T_SZ + (T_SZ - 1)];
        E_s[b][e] = C_table[tok * EMB + e];
    }
    __syncthreads();

    const int h    = blockIdx.x * 64 + (tid & 63);
    const int bsub = tid >> 6;
    const int r0   = bsub * 2;

    float ai[2], ag[2], ao[2];
    const float bi = b_i[h], bc = b_c[h], bo = b_o[h];
#pragma unroll
    for (int r = 0; r < 2; r++) { ai[r] = bi; ag[r] = bc; ao[r] = bo; }

#pragma unroll 4
    for (int e = 0; e < EMB; e++) {
        float ui = U_i[e * HID + h];
        float uc = U_c[e * HID + h];
        float uo = U_o[e * HID + h];
#pragma unroll
        for (int r = 0; r < 2; r++) {
            float ev = E_s[r0 + r][e];
            ai[r] = fmaf(ev, ui, ai[r]);
            ag[r] = fmaf(ev, uc, ag[r]);
            ao[r] = fmaf(ev, uo, ao[r]);
        }
    }

#pragma unroll
    for (int r = 0; r < 2; r++) {
        float i0 = 1.0f / (1.0f + __expf(-ai[r]));
        float g0 = tanhf(ag[r]);
        float o0 = 1.0f / (1.0f + __expf(-ao[r]));
        float c0 = i0 * g0;
        float h0 = o0 * tanhf(c0);
        g_h0[(b0 + r0 + r) * HID + h] = __float2bfloat16(h0);
    }
}

// ---------------------------------------------------------------------------
// Kernel 2: logits[256, 32000] = h0[256,256] @ W_w[32000,256]^T + b_out
// R12 champion skeleton at 256 THREADS (8 warps) -> 255 regs/thread.
//   Warp tile 64(M) x 64(N): wm = wid>>1 (0..3), wn = wid&1 (0..1).
//   acc[4][8][4] = 128 regs; ptxas has headroom to pipeline loads vs MMAs.
//   A-fragment LDSM duplication drops 4x -> 2x.
//   GRID = 125 CTAs, 2 balanced tiles each (bid, bid+125); 16 phases;
//   CHUNK_K=32 fp32; 4 buffers; wait_group 2; issue-before-compute;
//   2 decoupled wn-groups (128 thr) with named barriers.
// ---------------------------------------------------------------------------
#define BM      256
#define BN      128
#define ASTR    264              // A_s row stride in bf16 (528B = 33*16)
#define CHUNK_K 32
#define NCHUNK  8                // chunks per tile
#define NPHASE  16               // 2 tiles x 8 chunks
#define NBUF    4
#define BSTR    40               // B_s row stride in fp32 (160B = 10*16)
#define BBUF    (BN * BSTR)      // one B buffer, floats (5120)
#define GRID2   125
#define NTILES  (NCLS / BN)      // 250

__device__ __forceinline__ void cp16(void* dst_smem, const void* src) {
    uint32_t d = (uint32_t)__cvta_generic_to_shared(dst_smem);
    asm volatile("cp.async.cg.shared.global [%0], [%1], 16;" :: "r"(d), "l"(src));
}
__device__ __forceinline__ void cp_commit() {
    asm volatile("cp.async.commit_group;" ::: "memory");
}
__device__ __forceinline__ void cp_wait2() {
    asm volatile("cp.async.wait_group 2;" ::: "memory");
}
__device__ __forceinline__ void group_bar(int wn) {
    asm volatile("bar.sync %0, 128;" :: "r"(1 + wn) : "memory");
}

// Issue this wn-group's 64 rows of one B chunk into buffer `dst`.
// gidx in [0,128): 512 segs = 64 rows x 8 segs -> 4 cp.async per thread.
__device__ __forceinline__ void issue_b_rows(
    float* dst, const float* __restrict__ W_w, int n0, int ck,
    int wn, int gidx)
{
#pragma unroll
    for (int k = 0; k < 4; k++) {
        int idx = gidx + k * 128;          // 0..511
        int rl  = idx >> 3;                // local row 0..63
        int seg = idx & 7;                 // 8 segs * 16B = 128B = 32 floats
        int row = wn * 64 + rl;
        cp16(dst + row * BSTR + seg * 4,
             W_w + (size_t)(n0 + row) * HID + ck * CHUNK_K + seg * 4);
    }
}

__global__ void __launch_bounds__(256, 1) logits_kernel(
    const float* __restrict__ W_w, const float* __restrict__ b_out,
    float* __restrict__ out)
{
    extern __shared__ char smem_raw[];
    __nv_bfloat16* A_s = (__nv_bfloat16*)smem_raw;              // [256][ASTR]
    float*         B_s = (float*)(smem_raw + BM * ASTR * 2);    // 4*[128][BSTR]

    const int tid = threadIdx.x;
    const int bid = blockIdx.x;
    const int n0_t0 = bid * BN;                 // tile 0
    const int n0_t1 = (bid + GRID2) * BN;       // tile 1

    const int wid  = tid >> 5;
    const int lane = tid & 31;
    const int wm   = wid >> 1;      // 0..3 -> M offset wm*64
    const int wn   = wid & 1;       // 0..1 -> N offset wn*64 (B row group)
    const int gidx = wm * 32 + lane;           // group-local index 0..127
    const int gr   = lane >> 2;
    const int tig  = lane & 3;
    const int lm_row = (lane & 15);
    const int lm_col = ((lane >> 4) & 1) << 3;

    // --- A load: 8192 segs, 32 per thread ---
    {
        const char* src = (const char*)g_h0;
#pragma unroll
        for (int k = 0; k < 32; k++) {
            int idx = tid + k * 256;       // 8192 segs (256 rows x 32 segs)
            int row = idx >> 5;
            int seg = idx & 31;
            cp16((char*)A_s + row * (ASTR * 2) + seg * 16,
                 src + row * (HID * 2) + seg * 16);
        }
    }
    cp_commit();                                           // group 0: A
    issue_b_rows(B_s + 0 * BBUF, W_w, n0_t0, 0, wn, gidx); cp_commit();
    issue_b_rows(B_s + 1 * BBUF, W_w, n0_t0, 1, wn, gidx); cp_commit();
    issue_b_rows(B_s + 2 * BBUF, W_w, n0_t0, 2, wn, gidx); cp_commit();

    // One-time CTA sync: A + chunk0 complete, A visible to all warps.
    cp_wait2();
    __syncthreads();

    float acc[4][8][4];
#pragma unroll
    for (int mi = 0; mi < 4; mi++)
#pragma unroll
        for (int ni = 0; ni < 8; ni++)
#pragma unroll
            for (int r = 0; r < 4; r++) acc[mi][ni][r] = 0.0f;

#pragma unroll
    for (int g = 0; g < NPHASE; g++) {
        const int c = g & 7;                          // chunk within tile
        cp_wait2();          // own groups: chunk g resident
        group_bar(wn);       // group-wide: chunk-g loads visible

        // ---- issue chunk g+3 (own rows) BEFORE compute (safe: target buf
        //      last read in compute g-1, finished before this phase's bar) ----
        if (g + 3 < NPHASE) {
            int gi  = g + 3;
            int nn0 = (gi < NCHUNK) ? n0_t0 : n0_t1;
            issue_b_rows(B_s + (gi & 3) * BBUF, W_w, nn0, gi & 7, wn, gidx);
        }
        cp_commit();         // unconditional: exact group numbering

        // ---- compute 2 kk steps of chunk g from buf g&3 ----
        const float* Bb = B_s + (g & 3) * BBUF;
#pragma unroll
        for (int kkl = 0; kkl < CHUNK_K / 16; kkl++) {
            const int kbg = c * CHUNK_K + kkl * 16;   // K offset in A
            const int kbl = kkl * 16;                 // K offset in B buf
            uint32_t a[4][4];
#pragma unroll
            for (int mi = 0; mi < 4; mi++) {
                uint32_t addr = (uint32_t)__cvta_generic_to_shared(
                    &A_s[(wm * 64 + mi * 16 + lm_row) * ASTR + kbg + lm_col]);
                asm volatile(
                    "ldmatrix.sync.aligned.m8n8.x4.shared.b16 {%0,%1,%2,%3}, [%4];"
                    : "=r"(a[mi][0]), "=r"(a[mi][1]), "=r"(a[mi][2]), "=r"(a[mi][3])
                    : "r"(addr));
            }
            uint32_t bf[8][2];
#pragma unroll
            for (int ni = 0; ni < 8; ni++) {
                const float* p =
                    Bb + (wn * 64 + ni * 8 + gr) * BSTR + kbl + tig * 2;
                float2 f0 = *(const float2*)(p);
                float2 f1 = *(const float2*)(p + 8);
                __nv_bfloat162 p0 = __floats2bfloat162_rn(f0.x, f0.y);
                __nv_bfloat162 p1 = __floats2bfloat162_rn(f1.x, f1.y);
                bf[ni][0] = *(const uint32_t*)&p0;
                bf[ni][1] = *(const uint32_t*)&p1;
            }
#pragma unroll
            for (int mi = 0; mi < 4; mi++) {
#pragma unroll
                for (int ni = 0; ni < 8; ni++) {
                    asm volatile(
                        "mma.sync.aligned.m16n8k16.row.col.f32.bf16.bf16.f32 "
                        "{%0,%1,%2,%3}, {%4,%5,%6,%7}, {%8,%9}, {%0,%1,%2,%3};"
                        : "+f"(acc[mi][ni][0]), "+f"(acc[mi][ni][1]),
                          "+f"(acc[mi][ni][2]), "+f"(acc[mi][ni][3])
                        : "r"(a[mi][0]), "r"(a[mi][1]), "r"(a[mi][2]), "r"(a[mi][3]),
                          "r"(bf[ni][0]), "r"(bf[ni][1]));
                }
            }
        }

        // ---- tile epilogue after its last chunk (warp-local; no sync) ----
        if (c == NCHUNK - 1) {
            const int n0 = (g < NCHUNK) ? n0_t0 : n0_t1;
            float bo0[8], bo1[8];
#pragma unroll
            for (int ni = 0; ni < 8; ni++) {
                int col = n0 + wn * 64 + ni * 8 + tig * 2;
                bo0[ni] = b_out[col];
                bo1[ni] = b_out[col + 1];
            }
#pragma unroll
            for (int mi = 0; mi < 4; mi++) {
                int row = wm * 64 + mi * 16 + gr;
#pragma unroll
                for (int ni = 0; ni < 8; ni++) {
                    int col = n0 + wn * 64 + ni * 8 + tig * 2;
                    float2 v0 = make_float2(acc[mi][ni][0] + bo0[ni],
                                            acc[mi][ni][1] + bo1[ni]);
                    float2 v1 = make_float2(acc[mi][ni][2] + bo0[ni],
                                            acc[mi][ni][3] + bo1[ni]);
                    *(float2*)(&out[(size_t)row * NCLS + col])       = v0;
                    *(float2*)(&out[(size_t)(row + 8) * NCLS + col]) = v1;
                }
            }
#pragma unroll
            for (int mi = 0; mi < 4; mi++)
#pragma unroll
                for (int ni = 0; ni < 8; ni++)
#pragma unroll
                    for (int r = 0; r < 4; r++) acc[mi][ni][r] = 0.0f;
        }
    }
}

// ---------------------------------------------------------------------------
// Launcher
// Input order: 0=X 1=C_table 2=U_i 3=V_i 4=b_i 5=U_f 6=V_f 7=b_f
//  8=U_c 9=V_c 10=b_c 11=U_o 12=V_o 13=b_o 14..25=layer1 (unused) 26=W_w 27=b_out
// ---------------------------------------------------------------------------
extern "C" void kernel_launch(void* const* d_in, const int* in_sizes, int n_in,
                              void* d_out, int out_size)
{
    const int*   X       = (const int*)d_in[0];
    const float* C_table = (const float*)d_in[1];
    const float* U_i     = (const float*)d_in[2];
    const float* b_i     = (const float*)d_in[4];
    const float* U_c     = (const float*)d_in[8];
    const float* b_c     = (const float*)d_in[10];
    const float* U_o     = (const float*)d_in[11];
    const float* b_o     = (const float*)d_in[13];
    const float* W_w     = (const float*)d_in[26];
    const float* b_out   = (const float*)d_in[27];
    float* out = (float*)d_out;

    dim3 grid1(4, 32);
    lstm_h0_kernel<<<grid1, 256>>>(X, C_table, U_i, b_i, U_c, b_c, U_o, b_o);

    const int smem_bytes = BM * ASTR * 2 + NBUF * BBUF * (int)sizeof(float); // 217088
    cudaFuncSetAttribute(logits_kernel,
                         cudaFuncAttributeMaxDynamicSharedMemorySize, smem_bytes);
    logits_kernel<<<GRID2, 256, smem_bytes>>>(W_w, b_out, out);
}